// round 13
// baseline (speedup 1.0000x reference)
#include <cuda_runtime.h>
#include <cuda_fp16.h>

#define SEQ 4096
#define HID 1024
#define NCTA 32
#define NTHR 544            // 16 compute warps + 1 poller warp
#define EPSF 1e-12f

// Scratch (allocation-free rule: __device__ globals)
__device__ float g_Xn[SEQ * HID];              // normalized embeddings
__device__ float g_P[SEQ * HID];               // W_hi @ x_t + b, precomputed
// tagged h double buffer: one u64 per ROW-PAIR: hi32 = tag, lo32 = fp16x2 (rows 2s, 2s+1)
__device__ unsigned long long g_H16[2][HID / 2];

// ---------------- weak L2-cached ld/st (fast path) ----------------
__device__ __forceinline__ void ld_cg_v2(const unsigned long long* p,
                                         unsigned long long& a, unsigned long long& b) {
    asm volatile("ld.global.cg.v2.u64 {%0,%1}, [%2];" : "=l"(a), "=l"(b) : "l"(p) : "memory");
}
__device__ __forceinline__ void st_cg(unsigned long long* p, unsigned long long v) {
    asm volatile("st.global.cg.u64 [%0], %1;" :: "l"(p), "l"(v) : "memory");
}
// ---------------- strong relaxed load (progress-guarantee fallback only) ----------------
__device__ __forceinline__ unsigned long long ld_rlx(const unsigned long long* p) {
    unsigned long long v;
    asm volatile("ld.relaxed.gpu.global.u64 %0, [%1];" : "=l"(v) : "l"(p) : "memory");
    return v;
}

// ---------------- f32x2 packed helpers ----------------
__device__ __forceinline__ unsigned long long packff(float a, float b) {
    unsigned long long r;
    asm("mov.b64 %0, {%1,%2};" : "=l"(r) : "r"(__float_as_uint(a)), "r"(__float_as_uint(b)));
    return r;
}
__device__ __forceinline__ void fma2(unsigned long long& acc, unsigned long long w,
                                     unsigned long long h) {
    asm("fma.rn.f32x2 %0, %1, %2, %0;" : "+l"(acc) : "l"(w), "l"(h));
}
__device__ __forceinline__ float sum2(unsigned long long a, unsigned long long b) {
    unsigned long long s;
    asm("add.rn.f32x2 %0, %1, %2;" : "=l"(s) : "l"(a), "l"(b));
    unsigned lo, hi;
    asm("mov.b64 {%0,%1}, %2;" : "=r"(lo), "=r"(hi) : "l"(s));
    return __uint_as_float(lo) + __uint_as_float(hi);
}

// ---------------- fast tanh: 1 - 2/(e^{2x}+1) via ex2/rcp approx ----------------
__device__ __forceinline__ float fast_tanh(float x) {
    float e;
    asm("ex2.approx.f32 %0, %1;" : "=f"(e) : "f"(x * 2.8853900817779268f)); // 2*log2(e)
    float r;
    asm("rcp.approx.f32 %0, %1;" : "=f"(r) : "f"(e + 1.0f));
    return fmaf(-2.0f, r, 1.0f);
}

// ---------------- fp16x2 <-> float packing ----------------
__device__ __forceinline__ unsigned pack_h2(float a, float b) {
    __half2 h = __floats2half2_rn(a, b);
    return *reinterpret_cast<unsigned*>(&h);
}
__device__ __forceinline__ float2 unpack_h2(unsigned u) {
    __half2 h = *reinterpret_cast<__half2*>(&u);
    return __half22float2(h);
}

// ---------------- split-phase named barrier (id 1, NTHR arrivals) ----------------
__device__ __forceinline__ void bar_sync_1() {
    asm volatile("bar.sync 1, %0;" :: "n"(NTHR) : "memory");
}
__device__ __forceinline__ void bar_arrive_1() {
    asm volatile("bar.arrive 1, %0;" :: "n"(NTHR) : "memory");
}

// ---------------- init: h0 -> out[0], tagged fp16 buf[0] (tag 1), clear buf[1] ----------------
__global__ __launch_bounds__(512) void init_kernel(const float* __restrict__ h0,
                                                   float* __restrict__ out) {
    int i = threadIdx.x;                        // 512 threads: one row-pair each
    float a = h0[2 * i], b = h0[2 * i + 1];
    out[2 * i] = a; out[2 * i + 1] = b;
    g_H16[0][i] = (1ull << 32) | (unsigned long long)pack_h2(a, b);
    g_H16[1][i] = 0ull;
}

// ---------------- embedding + L2 normalize ----------------
__global__ __launch_bounds__(256) void embed_kernel(const int* __restrict__ src,
                                                    const float* __restrict__ W) {
    const int t   = blockIdx.x;
    const int tid = threadIdx.x;
    const float4* row = reinterpret_cast<const float4*>(W) + (size_t)src[t] * (HID / 4);
    float4 v = row[tid];
    float s = v.x * v.x + v.y * v.y + v.z * v.z + v.w * v.w;
    #pragma unroll
    for (int o = 16; o; o >>= 1) s += __shfl_xor_sync(0xffffffffu, s, o);
    __shared__ float red[8];
    if ((tid & 31) == 0) red[tid >> 5] = s;
    __syncthreads();
    float tot = red[0] + red[1] + red[2] + red[3] + red[4] + red[5] + red[6] + red[7];
    float rn = 1.0f / fmaxf(sqrtf(tot), EPSF);
    float4 o4 = make_float4(v.x * rn, v.y * rn, v.z * rn, v.w * rn);
    reinterpret_cast<float4*>(g_Xn)[(size_t)t * (HID / 4) + tid] = o4;
}

// ---------------- GEMM: g_P[m][n] = sum_k g_Xn[m][k] * W_hi[n][k] + b[n] ----------------
#define BM 128
#define BN 64
#define BK 32
__global__ __launch_bounds__(256) void gemm_kernel(const float* __restrict__ Bw,
                                                   const float* __restrict__ bias) {
    __shared__ float As[BK][BM + 4];
    __shared__ float Bs[BK][BN + 4];
    const int tid = threadIdx.x;
    const int m0 = blockIdx.y * BM;
    const int n0 = blockIdx.x * BN;
    const int ty = tid >> 4;
    const int tx = tid & 15;

    float acc[8][4];
    #pragma unroll
    for (int i = 0; i < 8; i++)
        #pragma unroll
        for (int j = 0; j < 4; j++) acc[i][j] = 0.0f;

    for (int k0 = 0; k0 < HID; k0 += BK) {
        #pragma unroll
        for (int i = 0; i < 4; i++) {
            int idx = tid + i * 256;
            int r = idx >> 3;
            int kq = idx & 7;
            float4 f = reinterpret_cast<const float4*>(g_Xn)[(size_t)(m0 + r) * (HID / 4) + (k0 >> 2) + kq];
            As[kq * 4 + 0][r] = f.x;
            As[kq * 4 + 1][r] = f.y;
            As[kq * 4 + 2][r] = f.z;
            As[kq * 4 + 3][r] = f.w;
        }
        #pragma unroll
        for (int i = 0; i < 2; i++) {
            int idx = tid + i * 256;
            int r = idx >> 3;
            int kq = idx & 7;
            float4 f = reinterpret_cast<const float4*>(Bw)[(size_t)(n0 + r) * (HID / 4) + (k0 >> 2) + kq];
            Bs[kq * 4 + 0][r] = f.x;
            Bs[kq * 4 + 1][r] = f.y;
            Bs[kq * 4 + 2][r] = f.z;
            Bs[kq * 4 + 3][r] = f.w;
        }
        __syncthreads();
        #pragma unroll
        for (int k = 0; k < BK; k++) {
            float4 a0 = *reinterpret_cast<const float4*>(&As[k][ty * 8]);
            float4 a1 = *reinterpret_cast<const float4*>(&As[k][ty * 8 + 4]);
            float4 b0 = *reinterpret_cast<const float4*>(&Bs[k][tx * 4]);
            float ar[8] = {a0.x, a0.y, a0.z, a0.w, a1.x, a1.y, a1.z, a1.w};
            float br[4] = {b0.x, b0.y, b0.z, b0.w};
            #pragma unroll
            for (int i = 0; i < 8; i++)
                #pragma unroll
                for (int j = 0; j < 4; j++)
                    acc[i][j] = fmaf(ar[i], br[j], acc[i][j]);
        }
        __syncthreads();
    }

    float4 bb = reinterpret_cast<const float4*>(bias)[(n0 >> 2) + tx];
    #pragma unroll
    for (int i = 0; i < 8; i++) {
        int m = m0 + ty * 8 + i;
        float4 o = make_float4(acc[i][0] + bb.x, acc[i][1] + bb.y,
                               acc[i][2] + bb.z, acc[i][3] + bb.w);
        reinterpret_cast<float4*>(g_P)[(size_t)m * (HID / 4) + (n0 >> 2) + tx] = o;
    }
}

// ---------------- persistent RNN: dedicated poller warp + split-phase barrier ----------------
// 32 CTAs x 17 warps (544 thr). Warps 0-15 compute (warp w owns rows
// c*32+2w, c*32+2w+1); warp 16 is a PURE poller: it sweeps all 512 tagged
// slots (16/lane, 8x v2.u64, MLP=8), stages fp16x2 words to parity smem,
// then bar.arrive (non-blocking) and immediately starts sweeping the NEXT
// step's tags -- detection overlaps compute+publish. Compute warps bar.sync
// (HW sleep) then dot/reduce/tanh/publish. Safety: poller cannot double-
// arrive (its next detect needs tag t+2, which requires this CTA's compute
// warps past phase t); smem overwrite at t+2 implies all local readers done
// with step t (distance-2 induction). Strong relaxed fallback every 64
// sweeps (progress guarantee). out[] keeps full fp32 values.
__global__ __launch_bounds__(NTHR) void rnn_kernel(const float* __restrict__ Whh,
                                                   float* __restrict__ out) {
    __shared__ unsigned shq[2][HID / 2];         // 4 KB: [parity][fp16x2 per row-pair]
    const int tid  = threadIdx.x;
    const int warp = tid >> 5;
    const int lane = tid & 31;
    const unsigned shb0 = (unsigned)__cvta_generic_to_shared(&shq[0][0]);

    if (warp == 16) {
        // ---------------- POLLER WARP ----------------
        for (int t = 0; t < SEQ; ++t) {
            const unsigned tag = (unsigned)(t + 1);   // tag of h_t
            const int par = t & 1;
            const unsigned long long* base = &g_H16[par][0] + (lane << 1);
            unsigned long long s0[8], s1[8];
            int spins = 0;
            for (;;) {
                #pragma unroll
                for (int k = 0; k < 8; k++)
                    ld_cg_v2(base + (k << 6), s0[k], s1[k]);
                unsigned ok = 1u;
                #pragma unroll
                for (int k = 0; k < 8; k++)
                    ok &= (unsigned)((unsigned)(s0[k] >> 32) == tag) &
                          (unsigned)((unsigned)(s1[k] >> 32) == tag);
                if (ok) break;
                if ((++spins & 63) == 0) {            // rare strong fallback (progress)
                    unsigned ok2 = 1u;
                    #pragma unroll
                    for (int k = 0; k < 8; k++) {
                        s0[k] = ld_rlx(base + (k << 6));
                        s1[k] = ld_rlx(base + (k << 6) + 1);
                        ok2 &= (unsigned)((unsigned)(s0[k] >> 32) == tag) &
                               (unsigned)((unsigned)(s1[k] >> 32) == tag);
                    }
                    if (ok2) break;
                }
            }
            // stage raw fp16x2 words to smem (8x st.shared.v2.u32), then arrive
            const unsigned sb = shb0 + ((unsigned)par << 11) + ((unsigned)lane << 3);
            #pragma unroll
            for (int k = 0; k < 8; k++) {
                asm volatile("st.shared.v2.u32 [%0], {%1,%2};"
                             :: "r"(sb + ((unsigned)k << 8)),
                                "r"((unsigned)s0[k]), "r"((unsigned)s1[k]));
            }
            bar_arrive_1();                           // non-blocking: resume polling
        }
        return;
    }

    // ---------------- COMPUTE WARPS (0-15) ----------------
    const int rowA = (blockIdx.x << 5) + (warp << 1);
    const int rowB = rowA + 1;
    const int myslot = (blockIdx.x << 4) + warp;      // publish slot = rowA/2

    // weights for both rows as packed f32x2 (16 u64 per row = 64 regs total)
    unsigned long long wA[16], wB[16];
    {
        const float4* wra = reinterpret_cast<const float4*>(Whh) + (size_t)rowA * (HID / 4);
        const float4* wrb = wra + (HID / 4);
        #pragma unroll
        for (int k = 0; k < 8; k++) {
            float4 a = wra[lane + (k << 5)];
            float4 b = wrb[lane + (k << 5)];
            wA[2 * k] = packff(a.x, a.y); wA[2 * k + 1] = packff(a.z, a.w);
            wB[2 * k] = packff(b.x, b.y); wB[2 * k + 1] = packff(b.z, b.w);
        }
    }

    float pa = g_P[rowA], pb = g_P[rowB];

    for (int t = 0; t < SEQ; ++t) {
        const int par = t & 1;

        // prefetch next-step P (independent of h)
        float pan = 0.f, pbn = 0.f;
        if (t + 1 < SEQ) {
            pan = g_P[(size_t)(t + 1) * HID + rowA];
            pbn = g_P[(size_t)(t + 1) * HID + rowB];
        }

        bar_sync_1();                                 // wait for poller staging (HW sleep)

        // dual-row dot product: LDS.v2.u32 (fp16x2 pair) -> cvt -> FFMA2
        const unsigned hb = shb0 + ((unsigned)par << 11);
        unsigned long long aA0 = 0ull, aA1 = 0ull, aB0 = 0ull, aB1 = 0ull;
        #pragma unroll
        for (int k = 0; k < 8; k++) {
            unsigned w0, w1;
            asm volatile("ld.shared.v2.u32 {%0,%1}, [%2];"
                         : "=r"(w0), "=r"(w1)
                         : "r"(hb + ((unsigned)(lane + (k << 5)) << 3)));
            float2 f01 = unpack_h2(w0);
            float2 f23 = unpack_h2(w1);
            unsigned long long h01 = packff(f01.x, f01.y);
            unsigned long long h23 = packff(f23.x, f23.y);
            fma2(aA0, wA[2 * k], h01); fma2(aA1, wA[2 * k + 1], h23);
            fma2(aB0, wB[2 * k], h01); fma2(aB1, wB[2 * k + 1], h23);
        }
        float sa = sum2(aA0, aA1);
        float sb = sum2(aB0, aB1);
        #pragma unroll
        for (int o = 16; o; o >>= 1) {
            sa += __shfl_xor_sync(0xffffffffu, sa, o);
            sb += __shfl_xor_sync(0xffffffffu, sb, o);
        }

        // lane 0: both tanhs, one 8B tagged fp16 publish FIRST, then fp32 out
        if (lane == 0) {
            float hA = fast_tanh(sa + pa);
            float hB = fast_tanh(sb + pb);
            unsigned long long wv = ((unsigned long long)(unsigned)(t + 2) << 32)
                                  | (unsigned long long)pack_h2(hA, hB);
            st_cg(&g_H16[(t + 1) & 1][myslot], wv);
            reinterpret_cast<float2*>(out + (size_t)(t + 1) * HID)[myslot] =
                make_float2(hA, hB);
        }
        pa = pan; pb = pbn;
    }
}

// ---------------- launch ----------------
extern "C" void kernel_launch(void* const* d_in, const int* in_sizes, int n_in,
                              void* d_out, int out_size) {
    const int*   src  = (const int*)  d_in[0];  // [4096]
    const float* W    = (const float*)d_in[1];  // [32000,1024]
    const float* h0   = (const float*)d_in[2];  // [1024]
    const float* W_hi = (const float*)d_in[3];  // [1024,1024]
    const float* W_hh = (const float*)d_in[4];  // [1024,1024]
    const float* b    = (const float*)d_in[5];  // [1024]
    float* out = (float*)d_out;                 // [4097,1024]

    init_kernel<<<1, 512>>>(h0, out);
    embed_kernel<<<SEQ, 256>>>(src, W);
    gemm_kernel<<<dim3(HID / BN, SEQ / BM), 256>>>(W_hi, b);
    rnn_kernel<<<NCTA, NTHR>>>(W_hh, out);
}

// round 15
// speedup vs baseline: 1.3778x; 1.3778x over previous
#include <cuda_runtime.h>
#include <cuda_fp16.h>

#define SEQ 4096
#define HID 1024
#define NCTA 32
#define EPSF 1e-12f

// Scratch (allocation-free rule: __device__ globals)
__device__ float g_Xn[SEQ * HID];              // normalized embeddings
__device__ float g_P[SEQ * HID];               // W_hi @ x_t + b, precomputed
// tagged h double buffer: one u64 per ROW-PAIR: hi32 = tag, lo32 = fp16x2 (rows 2s, 2s+1)
__device__ unsigned long long g_H16[2][HID / 2];

// ---------------- weak L2-cached ld/st (fast path) ----------------
__device__ __forceinline__ void ld_cg_v2(const unsigned long long* p,
                                         unsigned long long& a, unsigned long long& b) {
    asm volatile("ld.global.cg.v2.u64 {%0,%1}, [%2];" : "=l"(a), "=l"(b) : "l"(p) : "memory");
}
__device__ __forceinline__ void st_cg(unsigned long long* p, unsigned long long v) {
    asm volatile("st.global.cg.u64 [%0], %1;" :: "l"(p), "l"(v) : "memory");
}
// ---------------- strong relaxed load (progress-guarantee fallback only) ----------------
__device__ __forceinline__ unsigned long long ld_rlx(const unsigned long long* p) {
    unsigned long long v;
    asm volatile("ld.relaxed.gpu.global.u64 %0, [%1];" : "=l"(v) : "l"(p) : "memory");
    return v;
}

// ---------------- f32x2 packed helpers ----------------
__device__ __forceinline__ unsigned long long packff(float a, float b) {
    unsigned long long r;
    asm("mov.b64 %0, {%1,%2};" : "=l"(r) : "r"(__float_as_uint(a)), "r"(__float_as_uint(b)));
    return r;
}
__device__ __forceinline__ void fma2(unsigned long long& acc, unsigned long long w,
                                     unsigned long long h) {
    asm("fma.rn.f32x2 %0, %1, %2, %0;" : "+l"(acc) : "l"(w), "l"(h));
}
__device__ __forceinline__ float sum2(unsigned long long a, unsigned long long b) {
    unsigned long long s;
    asm("add.rn.f32x2 %0, %1, %2;" : "=l"(s) : "l"(a), "l"(b));
    unsigned lo, hi;
    asm("mov.b64 {%0,%1}, %2;" : "=r"(lo), "=r"(hi) : "l"(s));
    return __uint_as_float(lo) + __uint_as_float(hi);
}

// ---------------- fast tanh: 1 - 2/(e^{2x}+1) via ex2/rcp approx ----------------
__device__ __forceinline__ float fast_tanh(float x) {
    float e;
    asm("ex2.approx.f32 %0, %1;" : "=f"(e) : "f"(x * 2.8853900817779268f)); // 2*log2(e)
    float r;
    asm("rcp.approx.f32 %0, %1;" : "=f"(r) : "f"(e + 1.0f));
    return fmaf(-2.0f, r, 1.0f);
}

// ---------------- fp16x2 <-> float packing ----------------
__device__ __forceinline__ unsigned pack_h2(float a, float b) {
    __half2 h = __floats2half2_rn(a, b);
    return *reinterpret_cast<unsigned*>(&h);
}
__device__ __forceinline__ float2 unpack_h2(unsigned u) {
    __half2 h = *reinterpret_cast<__half2*>(&u);
    return __half22float2(h);
}

// ---------------- init: h0 -> out[0], tagged fp16 buf[0] (tag 1), clear buf[1] ----------------
__global__ __launch_bounds__(512) void init_kernel(const float* __restrict__ h0,
                                                   float* __restrict__ out) {
    int i = threadIdx.x;                        // 512 threads: one row-pair each
    float a = h0[2 * i], b = h0[2 * i + 1];
    out[2 * i] = a; out[2 * i + 1] = b;
    g_H16[0][i] = (1ull << 32) | (unsigned long long)pack_h2(a, b);
    g_H16[1][i] = 0ull;
}

// ---------------- embedding + L2 normalize ----------------
__global__ __launch_bounds__(256) void embed_kernel(const int* __restrict__ src,
                                                    const float* __restrict__ W) {
    const int t   = blockIdx.x;
    const int tid = threadIdx.x;
    const float4* row = reinterpret_cast<const float4*>(W) + (size_t)src[t] * (HID / 4);
    float4 v = row[tid];
    float s = v.x * v.x + v.y * v.y + v.z * v.z + v.w * v.w;
    #pragma unroll
    for (int o = 16; o; o >>= 1) s += __shfl_xor_sync(0xffffffffu, s, o);
    __shared__ float red[8];
    if ((tid & 31) == 0) red[tid >> 5] = s;
    __syncthreads();
    float tot = red[0] + red[1] + red[2] + red[3] + red[4] + red[5] + red[6] + red[7];
    float rn = 1.0f / fmaxf(sqrtf(tot), EPSF);
    float4 o4 = make_float4(v.x * rn, v.y * rn, v.z * rn, v.w * rn);
    reinterpret_cast<float4*>(g_Xn)[(size_t)t * (HID / 4) + tid] = o4;
}

// ---------------- GEMM: g_P[m][n] = sum_k g_Xn[m][k] * W_hi[n][k] + b[n] ----------------
#define BM 128
#define BN 64
#define BK 32
__global__ __launch_bounds__(256) void gemm_kernel(const float* __restrict__ Bw,
                                                   const float* __restrict__ bias) {
    __shared__ float As[BK][BM + 4];
    __shared__ float Bs[BK][BN + 4];
    const int tid = threadIdx.x;
    const int m0 = blockIdx.y * BM;
    const int n0 = blockIdx.x * BN;
    const int ty = tid >> 4;
    const int tx = tid & 15;

    float acc[8][4];
    #pragma unroll
    for (int i = 0; i < 8; i++)
        #pragma unroll
        for (int j = 0; j < 4; j++) acc[i][j] = 0.0f;

    for (int k0 = 0; k0 < HID; k0 += BK) {
        #pragma unroll
        for (int i = 0; i < 4; i++) {
            int idx = tid + i * 256;
            int r = idx >> 3;
            int kq = idx & 7;
            float4 f = reinterpret_cast<const float4*>(g_Xn)[(size_t)(m0 + r) * (HID / 4) + (k0 >> 2) + kq];
            As[kq * 4 + 0][r] = f.x;
            As[kq * 4 + 1][r] = f.y;
            As[kq * 4 + 2][r] = f.z;
            As[kq * 4 + 3][r] = f.w;
        }
        #pragma unroll
        for (int i = 0; i < 2; i++) {
            int idx = tid + i * 256;
            int r = idx >> 3;
            int kq = idx & 7;
            float4 f = reinterpret_cast<const float4*>(Bw)[(size_t)(n0 + r) * (HID / 4) + (k0 >> 2) + kq];
            Bs[kq * 4 + 0][r] = f.x;
            Bs[kq * 4 + 1][r] = f.y;
            Bs[kq * 4 + 2][r] = f.z;
            Bs[kq * 4 + 3][r] = f.w;
        }
        __syncthreads();
        #pragma unroll
        for (int k = 0; k < BK; k++) {
            float4 a0 = *reinterpret_cast<const float4*>(&As[k][ty * 8]);
            float4 a1 = *reinterpret_cast<const float4*>(&As[k][ty * 8 + 4]);
            float4 b0 = *reinterpret_cast<const float4*>(&Bs[k][tx * 4]);
            float ar[8] = {a0.x, a0.y, a0.z, a0.w, a1.x, a1.y, a1.z, a1.w};
            float br[4] = {b0.x, b0.y, b0.z, b0.w};
            #pragma unroll
            for (int i = 0; i < 8; i++)
                #pragma unroll
                for (int j = 0; j < 4; j++)
                    acc[i][j] = fmaf(ar[i], br[j], acc[i][j]);
        }
        __syncthreads();
    }

    float4 bb = reinterpret_cast<const float4*>(bias)[(n0 >> 2) + tx];
    #pragma unroll
    for (int i = 0; i < 8; i++) {
        int m = m0 + ty * 8 + i;
        float4 o = make_float4(acc[i][0] + bb.x, acc[i][1] + bb.y,
                               acc[i][2] + bb.z, acc[i][3] + bb.w);
        reinterpret_cast<float4*>(g_P)[(size_t)m * (HID / 4) + (n0 >> 2) + tx] = o;
    }
}

// ---------------- persistent RNN: R12 structure + fp32 staging by poller ----------------
// 32 CTAs x 16 warps (512 thr). Warp w of CTA c owns rows c*32+2w, c*32+2w+1.
// Sync channel: ONE u64 per row-pair = [tag32 | fp16x2] (8B-atomic, weak .cg).
// Warp 0 of each CTA polls ALL 512 slots (16/lane, 8x v2.u64, MLP=8), then
// CONVERTS fp16x2 -> fp32 and stages float4s. Lane L, chunk k polls slots
// (2L+64k, 2L+64k+1) = rows 4L+128k .. 4L+128k+3 -> fp32 byte offset
// (L<<4) + (k<<9). __syncthreads parks warp 0's spinning the moment staging
// is done (R13 lesson: never leave a spinner free-running). Compute warps
// run a cvt-free dot: 8x LDS.v2.u64 + 32 FFMA2 (fp16-unpack paid ONCE by
// warp 0 instead of by all 16 warps). Strong relaxed fallback every 64
// sweeps (progress). Parity double-buffered smem; distance-2 overwrite
// induction unchanged. out[] keeps fp32 values.
__global__ __launch_bounds__(512) void rnn_kernel(const float* __restrict__ Whh,
                                                  float* __restrict__ out) {
    __shared__ float shf[2][HID];                // 8 KB: [parity][h as fp32]
    const int tid  = threadIdx.x;
    const int warp = tid >> 5;
    const int lane = tid & 31;
    const int rowA = (blockIdx.x << 5) + (warp << 1);
    const int rowB = rowA + 1;
    const int myslot = (blockIdx.x << 4) + warp;   // publish slot = rowA/2

    // weights for both rows as packed f32x2 (16 u64 per row = 64 regs total)
    unsigned long long wA[16], wB[16];
    {
        const float4* wra = reinterpret_cast<const float4*>(Whh) + (size_t)rowA * (HID / 4);
        const float4* wrb = wra + (HID / 4);
        #pragma unroll
        for (int k = 0; k < 8; k++) {
            float4 a = wra[lane + (k << 5)];
            float4 b = wrb[lane + (k << 5)];
            wA[2 * k] = packff(a.x, a.y); wA[2 * k + 1] = packff(a.z, a.w);
            wB[2 * k] = packff(b.x, b.y); wB[2 * k + 1] = packff(b.z, b.w);
        }
    }

    const unsigned shb0 = (unsigned)__cvta_generic_to_shared(&shf[0][0]);
    float pa = g_P[rowA], pb = g_P[rowB];

    for (int t = 0; t < SEQ; ++t) {
        const unsigned tag = (unsigned)(t + 1);    // tag of h_t
        const int par = t & 1;

        // prefetch next-step P (independent of h)
        float pan = 0.f, pbn = 0.f;
        if (t + 1 < SEQ) {
            pan = g_P[(size_t)(t + 1) * HID + rowA];
            pbn = g_P[(size_t)(t + 1) * HID + rowB];
        }

        // 1) DETECTION + fp32 STAGING (warp 0 only)
        if (warp == 0) {
            const unsigned long long* base = &g_H16[par][0] + (lane << 1);
            unsigned long long s0[8], s1[8];
            int spins = 0;
            for (;;) {
                #pragma unroll
                for (int k = 0; k < 8; k++)
                    ld_cg_v2(base + (k << 6), s0[k], s1[k]);
                unsigned ok = 1u;
                #pragma unroll
                for (int k = 0; k < 8; k++)
                    ok &= (unsigned)((unsigned)(s0[k] >> 32) == tag) &
                          (unsigned)((unsigned)(s1[k] >> 32) == tag);
                if (ok) break;
                if ((++spins & 63) == 0) {         // rare strong fallback (progress)
                    unsigned ok2 = 1u;
                    #pragma unroll
                    for (int k = 0; k < 8; k++) {
                        s0[k] = ld_rlx(base + (k << 6));
                        s1[k] = ld_rlx(base + (k << 6) + 1);
                        ok2 &= (unsigned)((unsigned)(s0[k] >> 32) == tag) &
                               (unsigned)((unsigned)(s1[k] >> 32) == tag);
                    }
                    if (ok2) break;
                }
            }
            // convert fp16x2 -> fp32, stage float4:
            // rows 4L+128k..+3 -> byte offset (L<<4) + (k<<9)   [max 8176 < 8192]
            const unsigned sb = shb0 + ((unsigned)par << 12) + ((unsigned)lane << 4);
            #pragma unroll
            for (int k = 0; k < 8; k++) {
                float2 f01 = unpack_h2((unsigned)s0[k]);
                float2 f23 = unpack_h2((unsigned)s1[k]);
                asm volatile("st.shared.v4.f32 [%0], {%1,%2,%3,%4};"
                             :: "r"(sb + ((unsigned)k << 9)),
                                "f"(f01.x), "f"(f01.y), "f"(f23.x), "f"(f23.y));
            }
        }
        __syncthreads();                           // parks warp 0; releases 15 warps

        // 2) cvt-free dual-row dot: 8x LDS.v2.u64 + 32 FFMA2
        const unsigned hb = shb0 + ((unsigned)par << 12);
        unsigned long long aA0 = 0ull, aA1 = 0ull, aB0 = 0ull, aB1 = 0ull;
        #pragma unroll
        for (int k = 0; k < 8; k++) {
            unsigned long long h01, h23;
            asm volatile("ld.shared.v2.u64 {%0,%1}, [%2];"
                         : "=l"(h01), "=l"(h23)
                         : "r"(hb + ((unsigned)(lane + (k << 5)) << 4)));
            fma2(aA0, wA[2 * k], h01); fma2(aA1, wA[2 * k + 1], h23);
            fma2(aB0, wB[2 * k], h01); fma2(aB1, wB[2 * k + 1], h23);
        }
        float sa = sum2(aA0, aA1);
        float sb = sum2(aB0, aB1);
        #pragma unroll
        for (int o = 16; o; o >>= 1) {
            sa += __shfl_xor_sync(0xffffffffu, sa, o);
            sb += __shfl_xor_sync(0xffffffffu, sb, o);
        }

        // 3) parallel tanh: lane0 does row A, lane1 does row B; lane0 publishes
        float s  = (lane == 1) ? (sb + pb) : (sa + pa);
        float hv = fast_tanh(s);
        float hB = __shfl_sync(0xffffffffu, hv, 1);
        if (lane == 0) {
            unsigned long long wv = ((unsigned long long)(unsigned)(t + 2) << 32)
                                  | (unsigned long long)pack_h2(hv, hB);
            st_cg(&g_H16[(t + 1) & 1][myslot], wv);
            reinterpret_cast<float2*>(out + (size_t)(t + 1) * HID)[myslot] =
                make_float2(hv, hB);
        }
        pa = pan; pb = pbn;
    }
}

// ---------------- launch ----------------
extern "C" void kernel_launch(void* const* d_in, const int* in_sizes, int n_in,
                              void* d_out, int out_size) {
    const int*   src  = (const int*)  d_in[0];  // [4096]
    const float* W    = (const float*)d_in[1];  // [32000,1024]
    const float* h0   = (const float*)d_in[2];  // [1024]
    const float* W_hi = (const float*)d_in[3];  // [1024,1024]
    const float* W_hh = (const float*)d_in[4];  // [1024,1024]
    const float* b    = (const float*)d_in[5];  // [1024]
    float* out = (float*)d_out;                 // [4097,1024]

    init_kernel<<<1, 512>>>(h0, out);
    embed_kernel<<<SEQ, 256>>>(src, W);
    gemm_kernel<<<dim3(HID / BN, SEQ / BM), 256>>>(W_hi, b);
    rnn_kernel<<<NCTA, 512>>>(W_hh, out);
}

// round 16
// speedup vs baseline: 1.3825x; 1.0034x over previous
#include <cuda_runtime.h>
#include <cuda_fp16.h>

#define SEQ 4096
#define HID 1024
#define NCTA 32
#define EPSF 1e-12f

// Scratch (allocation-free rule: __device__ globals)
__device__ float g_Xn[SEQ * HID];              // normalized embeddings
__device__ float g_P[SEQ * HID];               // W_hi @ x_t + b, precomputed
// tagged h double buffer: one u64 per ROW-PAIR: hi32 = tag, lo32 = fp16x2 (rows 2s, 2s+1)
__device__ unsigned long long g_H16[2][HID / 2];

// ---------------- weak L2-cached ld/st (fast path) ----------------
__device__ __forceinline__ void ld_cg_v2(const unsigned long long* p,
                                         unsigned long long& a, unsigned long long& b) {
    asm volatile("ld.global.cg.v2.u64 {%0,%1}, [%2];" : "=l"(a), "=l"(b) : "l"(p) : "memory");
}
__device__ __forceinline__ void st_cg(unsigned long long* p, unsigned long long v) {
    asm volatile("st.global.cg.u64 [%0], %1;" :: "l"(p), "l"(v) : "memory");
}
// ---------------- strong relaxed load (progress-guarantee fallback only) ----------------
__device__ __forceinline__ unsigned long long ld_rlx(const unsigned long long* p) {
    unsigned long long v;
    asm volatile("ld.relaxed.gpu.global.u64 %0, [%1];" : "=l"(v) : "l"(p) : "memory");
    return v;
}

// ---------------- f32x2 packed helpers ----------------
__device__ __forceinline__ unsigned long long packff(float a, float b) {
    unsigned long long r;
    asm("mov.b64 %0, {%1,%2};" : "=l"(r) : "r"(__float_as_uint(a)), "r"(__float_as_uint(b)));
    return r;
}
__device__ __forceinline__ void fma2(unsigned long long& acc, unsigned long long w,
                                     unsigned long long h) {
    asm("fma.rn.f32x2 %0, %1, %2, %0;" : "+l"(acc) : "l"(w), "l"(h));
}
__device__ __forceinline__ float sum2(unsigned long long a, unsigned long long b) {
    unsigned long long s;
    asm("add.rn.f32x2 %0, %1, %2;" : "=l"(s) : "l"(a), "l"(b));
    unsigned lo, hi;
    asm("mov.b64 {%0,%1}, %2;" : "=r"(lo), "=r"(hi) : "l"(s));
    return __uint_as_float(lo) + __uint_as_float(hi);
}

// ---------------- fast tanh: 1 - 2/(e^{2x}+1) via ex2/rcp approx ----------------
__device__ __forceinline__ float fast_tanh(float x) {
    float e;
    asm("ex2.approx.f32 %0, %1;" : "=f"(e) : "f"(x * 2.8853900817779268f)); // 2*log2(e)
    float r;
    asm("rcp.approx.f32 %0, %1;" : "=f"(r) : "f"(e + 1.0f));
    return fmaf(-2.0f, r, 1.0f);
}

// ---------------- fp16x2 <-> float packing ----------------
__device__ __forceinline__ unsigned pack_h2(float a, float b) {
    __half2 h = __floats2half2_rn(a, b);
    return *reinterpret_cast<unsigned*>(&h);
}
__device__ __forceinline__ float2 unpack_h2(unsigned u) {
    __half2 h = *reinterpret_cast<__half2*>(&u);
    return __half22float2(h);
}

// ---------------- init: h0 -> out[0], tagged fp16 buf[0] (tag 1), clear buf[1] ----------------
__global__ __launch_bounds__(512) void init_kernel(const float* __restrict__ h0,
                                                   float* __restrict__ out) {
    int i = threadIdx.x;                        // 512 threads: one row-pair each
    float a = h0[2 * i], b = h0[2 * i + 1];
    out[2 * i] = a; out[2 * i + 1] = b;
    g_H16[0][i] = (1ull << 32) | (unsigned long long)pack_h2(a, b);
    g_H16[1][i] = 0ull;
}

// ---------------- embedding + L2 normalize ----------------
__global__ __launch_bounds__(256) void embed_kernel(const int* __restrict__ src,
                                                    const float* __restrict__ W) {
    const int t   = blockIdx.x;
    const int tid = threadIdx.x;
    const float4* row = reinterpret_cast<const float4*>(W) + (size_t)src[t] * (HID / 4);
    float4 v = row[tid];
    float s = v.x * v.x + v.y * v.y + v.z * v.z + v.w * v.w;
    #pragma unroll
    for (int o = 16; o; o >>= 1) s += __shfl_xor_sync(0xffffffffu, s, o);
    __shared__ float red[8];
    if ((tid & 31) == 0) red[tid >> 5] = s;
    __syncthreads();
    float tot = red[0] + red[1] + red[2] + red[3] + red[4] + red[5] + red[6] + red[7];
    float rn = 1.0f / fmaxf(sqrtf(tot), EPSF);
    float4 o4 = make_float4(v.x * rn, v.y * rn, v.z * rn, v.w * rn);
    reinterpret_cast<float4*>(g_Xn)[(size_t)t * (HID / 4) + tid] = o4;
}

// ---------------- GEMM: g_P[m][n] = sum_k g_Xn[m][k] * W_hi[n][k] + b[n] ----------------
#define BM 128
#define BN 64
#define BK 32
__global__ __launch_bounds__(256) void gemm_kernel(const float* __restrict__ Bw,
                                                   const float* __restrict__ bias) {
    __shared__ float As[BK][BM + 4];
    __shared__ float Bs[BK][BN + 4];
    const int tid = threadIdx.x;
    const int m0 = blockIdx.y * BM;
    const int n0 = blockIdx.x * BN;
    const int ty = tid >> 4;
    const int tx = tid & 15;

    float acc[8][4];
    #pragma unroll
    for (int i = 0; i < 8; i++)
        #pragma unroll
        for (int j = 0; j < 4; j++) acc[i][j] = 0.0f;

    for (int k0 = 0; k0 < HID; k0 += BK) {
        #pragma unroll
        for (int i = 0; i < 4; i++) {
            int idx = tid + i * 256;
            int r = idx >> 3;
            int kq = idx & 7;
            float4 f = reinterpret_cast<const float4*>(g_Xn)[(size_t)(m0 + r) * (HID / 4) + (k0 >> 2) + kq];
            As[kq * 4 + 0][r] = f.x;
            As[kq * 4 + 1][r] = f.y;
            As[kq * 4 + 2][r] = f.z;
            As[kq * 4 + 3][r] = f.w;
        }
        #pragma unroll
        for (int i = 0; i < 2; i++) {
            int idx = tid + i * 256;
            int r = idx >> 3;
            int kq = idx & 7;
            float4 f = reinterpret_cast<const float4*>(Bw)[(size_t)(n0 + r) * (HID / 4) + (k0 >> 2) + kq];
            Bs[kq * 4 + 0][r] = f.x;
            Bs[kq * 4 + 1][r] = f.y;
            Bs[kq * 4 + 2][r] = f.z;
            Bs[kq * 4 + 3][r] = f.w;
        }
        __syncthreads();
        #pragma unroll
        for (int k = 0; k < BK; k++) {
            float4 a0 = *reinterpret_cast<const float4*>(&As[k][ty * 8]);
            float4 a1 = *reinterpret_cast<const float4*>(&As[k][ty * 8 + 4]);
            float4 b0 = *reinterpret_cast<const float4*>(&Bs[k][tx * 4]);
            float ar[8] = {a0.x, a0.y, a0.z, a0.w, a1.x, a1.y, a1.z, a1.w};
            float br[4] = {b0.x, b0.y, b0.z, b0.w};
            #pragma unroll
            for (int i = 0; i < 8; i++)
                #pragma unroll
                for (int j = 0; j < 4; j++)
                    acc[i][j] = fmaf(ar[i], br[j], acc[i][j]);
        }
        __syncthreads();
    }

    float4 bb = reinterpret_cast<const float4*>(bias)[(n0 >> 2) + tx];
    #pragma unroll
    for (int i = 0; i < 8; i++) {
        int m = m0 + ty * 8 + i;
        float4 o = make_float4(acc[i][0] + bb.x, acc[i][1] + bb.y,
                               acc[i][2] + bb.z, acc[i][3] + bb.w);
        reinterpret_cast<float4*>(g_P)[(size_t)m * (HID / 4) + (n0 >> 2) + tx] = o;
    }
}

// ---------------- persistent RNN: R12 structure + fp32 staging by poller ----------------
// 32 CTAs x 16 warps (512 thr). Warp w of CTA c owns rows c*32+2w, c*32+2w+1.
// Sync channel: ONE u64 per row-pair = [tag32 | fp16x2] (8B-atomic, weak .cg).
// Warp 0 of each CTA polls ALL 512 slots (16/lane, 8x v2.u64, MLP=8), then
// CONVERTS fp16x2 -> fp32 and stages float4s. Lane L, chunk k polls slots
// (2L+64k, 2L+64k+1) = rows 4L+128k .. 4L+128k+3 -> fp32 byte offset
// (L<<4) + (k<<9). __syncthreads parks warp 0's spinning the moment staging
// is done (R13 lesson: never leave a spinner free-running). Compute warps
// run a cvt-free dot: 8x LDS.v2.u64 + 32 FFMA2 (fp16-unpack paid ONCE by
// warp 0 instead of by all 16 warps). Strong relaxed fallback every 64
// sweeps (progress). Parity double-buffered smem; distance-2 overwrite
// induction unchanged. out[] keeps fp32 values.
__global__ __launch_bounds__(512) void rnn_kernel(const float* __restrict__ Whh,
                                                  float* __restrict__ out) {
    __shared__ float shf[2][HID];                // 8 KB: [parity][h as fp32]
    const int tid  = threadIdx.x;
    const int warp = tid >> 5;
    const int lane = tid & 31;
    const int rowA = (blockIdx.x << 5) + (warp << 1);
    const int rowB = rowA + 1;
    const int myslot = (blockIdx.x << 4) + warp;   // publish slot = rowA/2

    // weights for both rows as packed f32x2 (16 u64 per row = 64 regs total)
    unsigned long long wA[16], wB[16];
    {
        const float4* wra = reinterpret_cast<const float4*>(Whh) + (size_t)rowA * (HID / 4);
        const float4* wrb = wra + (HID / 4);
        #pragma unroll
        for (int k = 0; k < 8; k++) {
            float4 a = wra[lane + (k << 5)];
            float4 b = wrb[lane + (k << 5)];
            wA[2 * k] = packff(a.x, a.y); wA[2 * k + 1] = packff(a.z, a.w);
            wB[2 * k] = packff(b.x, b.y); wB[2 * k + 1] = packff(b.z, b.w);
        }
    }

    const unsigned shb0 = (unsigned)__cvta_generic_to_shared(&shf[0][0]);
    float pa = g_P[rowA], pb = g_P[rowB];

    for (int t = 0; t < SEQ; ++t) {
        const unsigned tag = (unsigned)(t + 1);    // tag of h_t
        const int par = t & 1;

        // prefetch next-step P (independent of h)
        float pan = 0.f, pbn = 0.f;
        if (t + 1 < SEQ) {
            pan = g_P[(size_t)(t + 1) * HID + rowA];
            pbn = g_P[(size_t)(t + 1) * HID + rowB];
        }

        // 1) DETECTION + fp32 STAGING (warp 0 only)
        if (warp == 0) {
            const unsigned long long* base = &g_H16[par][0] + (lane << 1);
            unsigned long long s0[8], s1[8];
            int spins = 0;
            for (;;) {
                #pragma unroll
                for (int k = 0; k < 8; k++)
                    ld_cg_v2(base + (k << 6), s0[k], s1[k]);
                unsigned ok = 1u;
                #pragma unroll
                for (int k = 0; k < 8; k++)
                    ok &= (unsigned)((unsigned)(s0[k] >> 32) == tag) &
                          (unsigned)((unsigned)(s1[k] >> 32) == tag);
                if (ok) break;
                if ((++spins & 63) == 0) {         // rare strong fallback (progress)
                    unsigned ok2 = 1u;
                    #pragma unroll
                    for (int k = 0; k < 8; k++) {
                        s0[k] = ld_rlx(base + (k << 6));
                        s1[k] = ld_rlx(base + (k << 6) + 1);
                        ok2 &= (unsigned)((unsigned)(s0[k] >> 32) == tag) &
                               (unsigned)((unsigned)(s1[k] >> 32) == tag);
                    }
                    if (ok2) break;
                }
            }
            // convert fp16x2 -> fp32, stage float4:
            // rows 4L+128k..+3 -> byte offset (L<<4) + (k<<9)   [max 8176 < 8192]
            const unsigned sb = shb0 + ((unsigned)par << 12) + ((unsigned)lane << 4);
            #pragma unroll
            for (int k = 0; k < 8; k++) {
                float2 f01 = unpack_h2((unsigned)s0[k]);
                float2 f23 = unpack_h2((unsigned)s1[k]);
                asm volatile("st.shared.v4.f32 [%0], {%1,%2,%3,%4};"
                             :: "r"(sb + ((unsigned)k << 9)),
                                "f"(f01.x), "f"(f01.y), "f"(f23.x), "f"(f23.y));
            }
        }
        __syncthreads();                           // parks warp 0; releases 15 warps

        // 2) cvt-free dual-row dot: 8x LDS.v2.u64 + 32 FFMA2
        const unsigned hb = shb0 + ((unsigned)par << 12);
        unsigned long long aA0 = 0ull, aA1 = 0ull, aB0 = 0ull, aB1 = 0ull;
        #pragma unroll
        for (int k = 0; k < 8; k++) {
            unsigned long long h01, h23;
            asm volatile("ld.shared.v2.u64 {%0,%1}, [%2];"
                         : "=l"(h01), "=l"(h23)
                         : "r"(hb + ((unsigned)(lane + (k << 5)) << 4)));
            fma2(aA0, wA[2 * k], h01); fma2(aA1, wA[2 * k + 1], h23);
            fma2(aB0, wB[2 * k], h01); fma2(aB1, wB[2 * k + 1], h23);
        }
        float sa = sum2(aA0, aA1);
        float sb = sum2(aB0, aB1);
        #pragma unroll
        for (int o = 16; o; o >>= 1) {
            sa += __shfl_xor_sync(0xffffffffu, sa, o);
            sb += __shfl_xor_sync(0xffffffffu, sb, o);
        }

        // 3) parallel tanh: lane0 does row A, lane1 does row B; lane0 publishes
        float s  = (lane == 1) ? (sb + pb) : (sa + pa);
        float hv = fast_tanh(s);
        float hB = __shfl_sync(0xffffffffu, hv, 1);
        if (lane == 0) {
            unsigned long long wv = ((unsigned long long)(unsigned)(t + 2) << 32)
                                  | (unsigned long long)pack_h2(hv, hB);
            st_cg(&g_H16[(t + 1) & 1][myslot], wv);
            reinterpret_cast<float2*>(out + (size_t)(t + 1) * HID)[myslot] =
                make_float2(hv, hB);
        }
        pa = pan; pb = pbn;
    }
}

// ---------------- launch ----------------
extern "C" void kernel_launch(void* const* d_in, const int* in_sizes, int n_in,
                              void* d_out, int out_size) {
    const int*   src  = (const int*)  d_in[0];  // [4096]
    const float* W    = (const float*)d_in[1];  // [32000,1024]
    const float* h0   = (const float*)d_in[2];  // [1024]
    const float* W_hi = (const float*)d_in[3];  // [1024,1024]
    const float* W_hh = (const float*)d_in[4];  // [1024,1024]
    const float* b    = (const float*)d_in[5];  // [1024]
    float* out = (float*)d_out;                 // [4097,1024]

    init_kernel<<<1, 512>>>(h0, out);
    embed_kernel<<<SEQ, 256>>>(src, W);
    gemm_kernel<<<dim3(HID / BN, SEQ / BM), 256>>>(W_hi, b);
    rnn_kernel<<<NCTA, 512>>>(W_hh, out);
}